// round 14
// baseline (speedup 1.0000x reference)
#include <cuda_runtime.h>
#include <math.h>

// Problem constants
#define BB 4
#define NN 2048
#define DIM 512
#define HEADS 8
#define DH 64
#define HIDDEN 512          // HEADS*DH
#define THC 1536            // 3*HIDDEN

// ---------------- scratch (device globals: allocation-free rule) ----------
__device__ float    g_qkv[(size_t)BB * NN * THC];          // 48 MB
__device__ float    g_q  [(size_t)BB * HEADS * NN * DH];   // 16 MB
// fragment-major packed operands (tf32 bit patterns)
__device__ unsigned g_kp  [(size_t)BB * HEADS * NN * DH];  // 16 MB  K packed
__device__ unsigned g_vp  [(size_t)BB * HEADS * NN * DH];  // 16 MB  V packed
__device__ unsigned g_xp  [(size_t)BB * NN * DIM];         // 16 MB  x packed
__device__ unsigned g_wq_hi[(size_t)DIM * THC];            // 3 MB
__device__ unsigned g_wq_lo[(size_t)DIM * THC];            // 3 MB
__device__ unsigned g_mp  [(size_t)BB * NN * HIDDEN];      // 16 MB  mid packed
__device__ unsigned g_wo_hi[(size_t)HIDDEN * DIM];         // 1 MB

// inv_freq[i] = 10000^(-2i/64) = 10^(-i/8), correctly-rounded fp32
__constant__ float c_invfreq[32] = {
    1.0f,
    0.74989420933245582f, 0.56234132519034907f, 0.42169650342858220f,
    0.31622776601683794f, 0.23713737056616552f, 0.17782794100389228f,
    0.13335214321633240f, 0.1f,
    0.074989420933245582f, 0.056234132519034907f, 0.042169650342858220f,
    0.031622776601683794f, 0.023713737056616552f, 0.017782794100389228f,
    0.013335214321633240f, 0.01f,
    0.0074989420933245582f, 0.0056234132519034907f, 0.0042169650342858220f,
    0.0031622776601683794f, 0.0023713737056616552f, 0.0017782794100389228f,
    0.0013335214321633240f, 0.001f,
    0.00074989420933245582f, 0.00056234132519034907f, 0.00042169650342858220f,
    0.00031622776601683794f, 0.00023713737056616552f, 0.00017782794100389228f,
    0.00013335214321633240f
};

// ---------------- tf32 helpers ----------------
__device__ __forceinline__ unsigned cvt_tf32(float f) {
    unsigned r;
    asm("cvt.rna.tf32.f32 %0, %1;" : "=r"(r) : "f"(f));
    return r;
}

__device__ __forceinline__ void mma_tf32(float c[4],
                                         unsigned a0, unsigned a1,
                                         unsigned a2, unsigned a3,
                                         unsigned b0, unsigned b1) {
    asm volatile(
        "mma.sync.aligned.m16n8k8.row.col.f32.tf32.tf32.f32 "
        "{%0,%1,%2,%3}, {%4,%5,%6,%7}, {%8,%9}, {%0,%1,%2,%3};\n"
        : "+f"(c[0]), "+f"(c[1]), "+f"(c[2]), "+f"(c[3])
        : "r"(a0), "r"(a1), "r"(a2), "r"(a3), "r"(b0), "r"(b1));
}

__device__ __forceinline__ void cp16(void* dst_smem, const void* src_gmem) {
    unsigned s = (unsigned)__cvta_generic_to_shared(dst_smem);
    asm volatile("cp.async.cg.shared.global [%0], [%1], 16;"
                 :: "r"(s), "l"(src_gmem));
}
__device__ __forceinline__ void cp_commit() {
    asm volatile("cp.async.commit_group;");
}
__device__ __forceinline__ void cp_wait1() {
    asm volatile("cp.async.wait_group 1;");
}

// =====================================================================
// Pack kernels (proven): m16n8k8 fragment-major tf32 layout.
// =====================================================================
__global__ __launch_bounds__(256)
void pack_a(const float* __restrict__ src, unsigned* __restrict__ dst, int K)
{
    const int gw   = (blockIdx.x * 256 + threadIdx.x) >> 5;
    const int lane = threadIdx.x & 31;
    const int KB   = K >> 3;
    const int mb   = gw / KB;
    const int kb   = gw - mb * KB;
    const int qg   = lane >> 2, q = lane & 3;
    const float* s = src + (size_t)(mb * 16 + qg) * K + kb * 8 + q;
    uint4 o;
    o.x = cvt_tf32(s[0]);
    o.y = cvt_tf32(s[(size_t)8 * K]);
    o.z = cvt_tf32(s[4]);
    o.w = cvt_tf32(s[(size_t)8 * K + 4]);
    *(uint4*)&dst[(size_t)gw * 128 + lane * 4] = o;
}

__global__ __launch_bounds__(256)
void pack_b(const float* __restrict__ src, unsigned* __restrict__ hi,
            unsigned* __restrict__ lo, int K, int N)
{
    const int gw   = (blockIdx.x * 256 + threadIdx.x) >> 5;
    const int lane = threadIdx.x & 31;
    const int KB2  = K >> 4;
    const int nb   = gw / KB2;
    const int kb2  = gw - nb * KB2;
    const int qg   = lane >> 2, q = lane & 3;
    const float* s = src + (size_t)(kb2 * 16 + q) * N + nb * 8 + qg;
    float v0 = s[0], v1 = s[(size_t)4 * N], v2 = s[(size_t)8 * N],
          v3 = s[(size_t)12 * N];
    uint4 h;
    h.x = cvt_tf32(v0); h.y = cvt_tf32(v1);
    h.z = cvt_tf32(v2); h.w = cvt_tf32(v3);
    *(uint4*)&hi[(size_t)gw * 128 + lane * 4] = h;
    if (lo) {
        uint4 l;
        l.x = cvt_tf32(v0 - __uint_as_float(h.x));
        l.y = cvt_tf32(v1 - __uint_as_float(h.y));
        l.z = cvt_tf32(v2 - __uint_as_float(h.z));
        l.w = cvt_tf32(v3 - __uint_as_float(h.w));
        *(uint4*)&lo[(size_t)gw * 128 + lane * 4] = l;
    }
}

// =====================================================================
// Packed tensor-core GEMM, WIDE warp M-tile (32 rows/warp).
// Block tile 256m x 64n, 256 threads (8 warps). K-step 32.
// 3-stage cp.async pipeline, ONE barrier per iter.
// B fragments now feed 2x the mma per load (LDS/mma: 0.56 -> 0.31).
// smem: PB=2 144KB, PB=1 120KB -> 1 block/SM.
// =====================================================================
#define ABUF2 8192   // 16 mb-blocks x 4 kk x 128 words
#define BBUF2 2048   // 8 nb x 2 kb2 x 128 words

template<int PB>
__global__ __launch_bounds__(256)
void pgemm(const unsigned* __restrict__ Ap, const unsigned* __restrict__ Bh,
           const unsigned* __restrict__ Bl, float* __restrict__ C,
           int M, int Nc, int K)
{
    extern __shared__ unsigned sm[];
    unsigned* As  = sm;                          // [3][ABUF2]
    unsigned* Bhs = sm + 3 * ABUF2;              // [3][BBUF2]
    unsigned* Bls = sm + 3 * ABUF2 + 3 * BBUF2;  // [3][BBUF2] (PB==2)

    const int tid  = threadIdx.x;
    const int lane = tid & 31;
    const int w    = tid >> 5;
    const int qg   = lane >> 2;
    const int q    = lane & 3;
    const int m0   = blockIdx.y * 256;
    const int n0   = blockIdx.x * 64;
    const int KB   = K >> 3;
    const int KB2  = K >> 4;
    const int NK   = K >> 5;

    const unsigned* Ag  = Ap + (size_t)(m0 >> 4) * KB * 128;
    const unsigned* Bhg = Bh + (size_t)(n0 >> 3) * KB2 * 128;
    const unsigned* Blg = (PB == 2) ? Bl + (size_t)(n0 >> 3) * KB2 * 128
                                    : (const unsigned*)0;

    // copy indices: A: 16 mb-regions of 512 words; 16 threads each, 32 words/thread
    const int amb  = tid >> 4;           // 0..15
    const int aoff = (tid & 15) * 32;    // word offset in 512-word region
    // B: 8 nb-regions of 256 words; 32 threads each, 8 words/thread
    const int bnb  = tid >> 5;
    const int boff = (tid & 31) * 8;

    auto issue_tile = [&](int it, int p) {
        const unsigned* ga = Ag + ((size_t)amb * KB + it * 4) * 128 + aoff;
        unsigned* da = As + p * ABUF2 + amb * 512 + aoff;
#pragma unroll
        for (int s = 0; s < 8; ++s)
            cp16(da + s * 4, ga + s * 4);
        const unsigned* gb = Bhg + ((size_t)bnb * KB2 + it * 2) * 128 + boff;
        unsigned* db = Bhs + p * BBUF2 + bnb * 256 + boff;
        cp16(db,     gb);
        cp16(db + 4, gb + 4);
        if (PB == 2) {
            const unsigned* gl = Blg + ((size_t)bnb * KB2 + it * 2) * 128 + boff;
            unsigned* dl = Bls + p * BBUF2 + bnb * 256 + boff;
            cp16(dl,     gl);
            cp16(dl + 4, gl + 4);
        }
        cp_commit();
    };

    float C_[2][8][4];
#pragma unroll
    for (int g = 0; g < 2; ++g)
#pragma unroll
        for (int nt = 0; nt < 8; ++nt)
#pragma unroll
            for (int j = 0; j < 4; ++j) C_[g][nt][j] = 0.f;

    issue_tile(0, 0);
    issue_tile(1, 1);
    cp_wait1();
    __syncthreads();

    for (int it = 0; it < NK; ++it) {
        const int p = it % 3;
        const int itn = (it + 2 < NK) ? it + 2 : NK - 1;
        issue_tile(itn, (it + 2) % 3);

        uint4 af[2][4];
#pragma unroll
        for (int g = 0; g < 2; ++g)
#pragma unroll
            for (int kk = 0; kk < 4; ++kk)
                af[g][kk] = *(const uint4*)
                    &As[p * ABUF2 + (w * 2 + g) * 512 + kk * 128 + lane * 4];

#pragma unroll
        for (int nt = 0; nt < 8; ++nt) {
            const unsigned* bb = &Bhs[p * BBUF2 + nt * 256 + lane * 4];
            uint4 b0 = *(const uint4*)bb;
            uint4 b1 = *(const uint4*)(bb + 128);
#pragma unroll
            for (int g = 0; g < 2; ++g) {
                mma_tf32(C_[g][nt], af[g][0].x, af[g][0].y, af[g][0].z, af[g][0].w, b0.x, b0.y);
                mma_tf32(C_[g][nt], af[g][1].x, af[g][1].y, af[g][1].z, af[g][1].w, b0.z, b0.w);
                mma_tf32(C_[g][nt], af[g][2].x, af[g][2].y, af[g][2].z, af[g][2].w, b1.x, b1.y);
                mma_tf32(C_[g][nt], af[g][3].x, af[g][3].y, af[g][3].z, af[g][3].w, b1.z, b1.w);
            }
            if (PB == 2) {
                const unsigned* bl = &Bls[p * BBUF2 + nt * 256 + lane * 4];
                uint4 l0 = *(const uint4*)bl;
                uint4 l1 = *(const uint4*)(bl + 128);
#pragma unroll
                for (int g = 0; g < 2; ++g) {
                    mma_tf32(C_[g][nt], af[g][0].x, af[g][0].y, af[g][0].z, af[g][0].w, l0.x, l0.y);
                    mma_tf32(C_[g][nt], af[g][1].x, af[g][1].y, af[g][1].z, af[g][1].w, l0.z, l0.w);
                    mma_tf32(C_[g][nt], af[g][2].x, af[g][2].y, af[g][2].z, af[g][2].w, l1.x, l1.y);
                    mma_tf32(C_[g][nt], af[g][3].x, af[g][3].y, af[g][3].z, af[g][3].w, l1.z, l1.w);
                }
            }
        }

        cp_wait1();
        __syncthreads();
    }

    // ---- epilogue ----
#pragma unroll
    for (int g = 0; g < 2; ++g) {
        size_t row = (size_t)(m0 + w * 32 + g * 16 + qg);
#pragma unroll
        for (int nt = 0; nt < 8; ++nt) {
            int col = n0 + nt * 8 + 2 * q;
            *(float2*)&C[row * Nc + col] =
                make_float2(C_[g][nt][0], C_[g][nt][1]);
            *(float2*)&C[(row + 8) * Nc + col] =
                make_float2(C_[g][nt][2], C_[g][nt][3]);
        }
    }
}

#define PGEMM_SMEM_2 (4 * (3 * ABUF2 + 3 * BBUF2 * 2))   // 147456 B
#define PGEMM_SMEM_1 (4 * (3 * ABUF2 + 3 * BBUF2))       // 122880 B

// =====================================================================
// QKV split + rotary (+ q scale). Q row-major; K/V fragment-packed.
// (unchanged from R13 — proven)
// =====================================================================
__global__ __launch_bounds__(256)
void qkv_transform()
{
    const int idx  = blockIdx.x * 256 + threadIdx.x;
    const int pair = idx & 31;
    const int n    = (idx >> 5) & (NN - 1);
    const int bh   = idx >> 16;
    const int b    = bh >> 3;
    const int h    = bh & 7;

    const float* src = g_qkv + (size_t)(b * NN + n) * THC;
    const int col = h * DH + pair * 2;

    float2 qv = *(const float2*)&src[col];
    float2 kv = *(const float2*)&src[HIDDEN + col];
    float2 vv = *(const float2*)&src[2 * HIDDEN + col];

    float fr = (float)n * c_invfreq[pair];
    float sn, cs;
    sincosf(fr, &sn, &cs);

    const float scale = 0.125f;
    float oq0 = (qv.x * cs - qv.y * sn) * scale;
    float oq1 = (qv.y * cs + qv.x * sn) * scale;
    float ok0 = kv.x * cs - kv.y * sn;
    float ok1 = kv.y * cs + kv.x * sn;

    const int d0 = pair * 2;
    const size_t bhbase = (size_t)bh * (NN * DH);

    size_t o = bhbase + (size_t)n * DH + d0;
    g_q[o] = oq0; g_q[o + 1] = oq1;

    {
        const int qgk = n & 7, nbk = n >> 3;
        const int kb2 = d0 >> 4;
        size_t kbase = bhbase + ((size_t)nbk * 4 + kb2) * 128;
        int w0 = ((qgk << 2) | (d0 & 3)) * 4 + ((d0 & 15) >> 2);
        int w1 = ((qgk << 2) | ((d0 + 1) & 3)) * 4 + (((d0 + 1) & 15) >> 2);
        g_kp[kbase + w0] = cvt_tf32(ok0);
        g_kp[kbase + w1] = cvt_tf32(ok1);
    }

    {
        const int qv_ = n & 3, rv = (n & 15) >> 2, kb2v = n >> 4;
        const int nb0 = d0 >> 3, qg0 = d0 & 7;
        size_t vbase = bhbase + ((size_t)nb0 * 128 + kb2v) * 128;
        g_vp[vbase + ((qg0 << 2) | qv_) * 4 + rv]       = cvt_tf32(vv.x);
        g_vp[vbase + (((qg0 + 1) << 2) | qv_) * 4 + rv] = cvt_tf32(vv.y);
    }
}

// =====================================================================
// Fused flash attention, tf32 tensor cores, pre-packed K/V.
// (unchanged from R13 — proven)
// =====================================================================
#define CHUNK_WORDS 4096
#define ATTN_SMEM (3 * CHUNK_WORDS * 4)   // 49152 B

__global__ __launch_bounds__(256, 2)
void attn_tf32(const float* __restrict__ bias)
{
    extern __shared__ unsigned sm[];

    const int tid  = threadIdx.x;
    const int lane = tid & 31;
    const int w    = tid >> 5;
    const int qg   = lane >> 2;
    const int q    = lane & 3;
    const int qblk = blockIdx.x * 128;
    const int h    = blockIdx.y;
    const int b    = blockIdx.z;
    const int bh   = b * HEADS + h;
    const unsigned* Kbh = g_kp + (size_t)bh * (NN * DH);
    const unsigned* Vbh = g_vp + (size_t)bh * (NN * DH);
    const float* biasw = bias + (size_t)h * NN * NN
                              + (size_t)(qblk + w * 16) * NN;

    const int koff = tid * 8;
    const int vreg = tid >> 5;
    const int voff = (tid & 31) * 8;

    auto issue_chunk = [&](int j, int p) {
        unsigned* dst = sm + p * CHUNK_WORDS;
        const unsigned* sk = Kbh + (size_t)j * 2048 + koff;
        cp16(dst + koff,     sk);
        cp16(dst + koff + 4, sk + 4);
        unsigned* dv = dst + 2048 + vreg * 256 + voff;
        const unsigned* sv = Vbh + ((size_t)vreg * 128 + j * 2) * 128 + voff;
        cp16(dv,     sv);
        cp16(dv + 4, sv + 4);
        cp_commit();
    };

    unsigned qa[8][4];
    {
        const float* Qp = g_q + (size_t)bh * (NN * DH)
                        + (size_t)(qblk + w * 16) * DH;
#pragma unroll
        for (int kc = 0; kc < 8; ++kc) {
            qa[kc][0] = cvt_tf32(Qp[(size_t)qg       * DH + kc * 8 + q]);
            qa[kc][1] = cvt_tf32(Qp[(size_t)(qg + 8) * DH + kc * 8 + q]);
            qa[kc][2] = cvt_tf32(Qp[(size_t)qg       * DH + kc * 8 + q + 4]);
            qa[kc][3] = cvt_tf32(Qp[(size_t)(qg + 8) * DH + kc * 8 + q + 4]);
        }
    }

    issue_chunk(0, 0);
    issue_chunk(1, 1);

    float S[4][4];
#pragma unroll
    for (int t = 0; t < 4; ++t) {
        float2 blo = *(const float2*)&biasw[(size_t)qg       * NN + t * 8 + 2 * q];
        float2 bhi = *(const float2*)&biasw[(size_t)(qg + 8) * NN + t * 8 + 2 * q];
        S[t][0] = blo.x; S[t][1] = blo.y;
        S[t][2] = bhi.x; S[t][3] = bhi.y;
    }

    cp_wait1();
    __syncthreads();

    float O[8][4];
#pragma unroll
    for (int n = 0; n < 8; ++n)
#pragma unroll
        for (int j = 0; j < 4; ++j) O[n][j] = 0.f;
    float m0 = -INFINITY, m1 = -INFINITY, l0 = 0.f, l1 = 0.f;

    const int srcA = (lane & ~3) | (q >> 1);
    const int srcB = srcA | 2;

    for (int j = 0; j < 64; ++j) {
        const int p = j % 3;
        issue_chunk((j + 2 < 64) ? j + 2 : 63, (j + 2) % 3);

        const unsigned* KF = sm + p * CHUNK_WORDS;
#pragma unroll
        for (int t = 0; t < 4; ++t) {
            uint4 k0 = *(const uint4*)&KF[t * 512 +   0 + lane * 4];
            uint4 k1 = *(const uint4*)&KF[t * 512 + 128 + lane * 4];
            uint4 k2 = *(const uint4*)&KF[t * 512 + 256 + lane * 4];
            uint4 k3 = *(const uint4*)&KF[t * 512 + 384 + lane * 4];
            mma_tf32(S[t], qa[0][0], qa[0][1], qa[0][2], qa[0][3], k0.x, k0.y);
            mma_tf32(S[t], qa[1][0], qa[1][1], qa[1][2], qa[1][3], k0.z, k0.w);
            mma_tf32(S[t], qa[2][0], qa[2][1], qa[2][2], qa[2][3], k1.x, k1.y);
            mma_tf32(S[t], qa[3][0], qa[3][1], qa[3][2], qa[3][3], k1.z, k1.w);
            mma_tf32(S[t], qa[4][0], qa[4][1], qa[4][2], qa[4][3], k2.x, k2.y);
            mma_tf32(S[t], qa[5][0], qa[5][1], qa[5][2], qa[5][3], k2.z, k2.w);
            mma_tf32(S[t], qa[6][0], qa[6][1], qa[6][2], qa[6][3], k3.x, k3.y);
            mma_tf32(S[t], qa[7][0], qa[7][1], qa[7][2], qa[7][3], k3.z, k3.w);
        }

        float cm0 = -INFINITY, cm1 = -INFINITY;
#pragma unroll
        for (int t = 0; t < 4; ++t) {
            cm0 = fmaxf(cm0, fmaxf(S[t][0], S[t][1]));
            cm1 = fmaxf(cm1, fmaxf(S[t][2], S[t][3]));
        }
        cm0 = fmaxf(cm0, __shfl_xor_sync(0xffffffffu, cm0, 1));
        cm0 = fmaxf(cm0, __shfl_xor_sync(0xffffffffu, cm0, 2));
        cm1 = fmaxf(cm1, __shfl_xor_sync(0xffffffffu, cm1, 1));
        cm1 = fmaxf(cm1, __shfl_xor_sync(0xffffffffu, cm1, 2));

        float mn0 = fmaxf(m0, cm0), mn1 = fmaxf(m1, cm1);
        float al0 = __expf(m0 - mn0), al1 = __expf(m1 - mn1);
        m0 = mn0; m1 = mn1;

        float s0 = 0.f, s1 = 0.f;
#pragma unroll
        for (int t = 0; t < 4; ++t) {
            S[t][0] = __expf(S[t][0] - mn0);
            S[t][1] = __expf(S[t][1] - mn0);
            S[t][2] = __expf(S[t][2] - mn1);
            S[t][3] = __expf(S[t][3] - mn1);
            s0 += S[t][0] + S[t][1];
            s1 += S[t][2] + S[t][3];
        }
        s0 += __shfl_xor_sync(0xffffffffu, s0, 1);
        s0 += __shfl_xor_sync(0xffffffffu, s0, 2);
        s1 += __shfl_xor_sync(0xffffffffu, s1, 1);
        s1 += __shfl_xor_sync(0xffffffffu, s1, 2);
        l0 = l0 * al0 + s0;
        l1 = l1 * al1 + s1;
#pragma unroll
        for (int n = 0; n < 8; ++n) {
            O[n][0] *= al0; O[n][1] *= al0;
            O[n][2] *= al1; O[n][3] *= al1;
        }

        unsigned pf[4][4];
#pragma unroll
        for (int t = 0; t < 4; ++t) {
            unsigned p0 = cvt_tf32(S[t][0]);
            unsigned p1 = cvt_tf32(S[t][1]);
            unsigned p2 = cvt_tf32(S[t][2]);
            unsigned p3 = cvt_tf32(S[t][3]);
            unsigned u0 = __shfl_sync(0xffffffffu, p0, srcA);
            unsigned u1 = __shfl_sync(0xffffffffu, p1, srcA);
            unsigned v0 = __shfl_sync(0xffffffffu, p0, srcB);
            unsigned v1 = __shfl_sync(0xffffffffu, p1, srcB);
            unsigned w0 = __shfl_sync(0xffffffffu, p2, srcA);
            unsigned w1 = __shfl_sync(0xffffffffu, p3, srcA);
            unsigned x0 = __shfl_sync(0xffffffffu, p2, srcB);
            unsigned x1 = __shfl_sync(0xffffffffu, p3, srcB);
            pf[t][0] = (q & 1) ? u1 : u0;
            pf[t][1] = (q & 1) ? w1 : w0;
            pf[t][2] = (q & 1) ? v1 : v0;
            pf[t][3] = (q & 1) ? x1 : x0;
        }

        const unsigned* VF = sm + p * CHUNK_WORDS + 2048;
#pragma unroll
        for (int nt = 0; nt < 8; ++nt) {
            uint4 v0 = *(const uint4*)&VF[nt * 256 +   0 + lane * 4];
            uint4 v1 = *(const uint4*)&VF[nt * 256 + 128 + lane * 4];
            mma_tf32(O[nt], pf[0][0], pf[0][1], pf[0][2], pf[0][3], v0.x, v0.y);
            mma_tf32(O[nt], pf[1][0], pf[1][1], pf[1][2], pf[1][3], v0.z, v0.w);
            mma_tf32(O[nt], pf[2][0], pf[2][1], pf[2][2], pf[2][3], v1.x, v1.y);
            mma_tf32(O[nt], pf[3][0], pf[3][1], pf[3][2], pf[3][3], v1.z, v1.w);
        }

        {
            const int j0n = ((j + 1 < 64) ? j + 1 : 63) * 32;
#pragma unroll
            for (int t = 0; t < 4; ++t) {
                float2 blo = *(const float2*)
                    &biasw[(size_t)qg       * NN + j0n + t * 8 + 2 * q];
                float2 bhi = *(const float2*)
                    &biasw[(size_t)(qg + 8) * NN + j0n + t * 8 + 2 * q];
                S[t][0] = blo.x; S[t][1] = blo.y;
                S[t][2] = bhi.x; S[t][3] = bhi.y;
            }
        }

        cp_wait1();
        __syncthreads();
    }

    const float il0 = 1.f / l0, il1 = 1.f / l1;
    const int mb = (b * NN + qblk + w * 16) >> 4;
#pragma unroll
    for (int nt = 0; nt < 8; ++nt) {
        unsigned f0 = __float_as_uint(O[nt][0] * il0);
        unsigned f1 = __float_as_uint(O[nt][1] * il0);
        unsigned f2 = __float_as_uint(O[nt][2] * il1);
        unsigned f3 = __float_as_uint(O[nt][3] * il1);
        unsigned u0 = __shfl_sync(0xffffffffu, f0, srcA);
        unsigned u1 = __shfl_sync(0xffffffffu, f1, srcA);
        unsigned w0 = __shfl_sync(0xffffffffu, f2, srcA);
        unsigned w1 = __shfl_sync(0xffffffffu, f3, srcA);
        unsigned x0 = __shfl_sync(0xffffffffu, f0, srcB);
        unsigned x1 = __shfl_sync(0xffffffffu, f1, srcB);
        unsigned y0 = __shfl_sync(0xffffffffu, f2, srcB);
        unsigned y1 = __shfl_sync(0xffffffffu, f3, srcB);
        uint4 o;
        o.x = cvt_tf32(__uint_as_float((q & 1) ? u1 : u0));
        o.y = cvt_tf32(__uint_as_float((q & 1) ? w1 : w0));
        o.z = cvt_tf32(__uint_as_float((q & 1) ? x1 : x0));
        o.w = cvt_tf32(__uint_as_float((q & 1) ? y1 : y0));
        const int kb = h * 8 + nt;
        *(uint4*)&g_mp[((size_t)mb * (HIDDEN / 8) + kb) * 128 + lane * 4] = o;
    }
}

// =====================================================================
extern "C" void kernel_launch(void* const* d_in, const int* in_sizes, int n_in,
                              void* d_out, int out_size)
{
    const float *x = nullptr, *bias = nullptr, *wqkv = nullptr, *wout = nullptr;
    for (int i = 0; i < n_in; ++i) {
        switch (in_sizes[i]) {
            case 4194304:  x    = (const float*)d_in[i]; break;  // x [4,2048,512]
            case 33554432: bias = (const float*)d_in[i]; break;  // pos_bias [8,2048,2048]
            case 786432:   wqkv = (const float*)d_in[i]; break;  // W_qkv [512,1536]
            case 262144:   wout = (const float*)d_in[i]; break;  // W_out [512,512]
        }
    }

    void *p_qkv = nullptr;
    void *p_xp = nullptr, *p_wqh = nullptr, *p_wql = nullptr;
    void *p_mp = nullptr, *p_woh = nullptr;
    cudaGetSymbolAddress(&p_qkv, g_qkv);
    cudaGetSymbolAddress(&p_xp,  g_xp);
    cudaGetSymbolAddress(&p_wqh, g_wq_hi);
    cudaGetSymbolAddress(&p_wql, g_wq_lo);
    cudaGetSymbolAddress(&p_mp,  g_mp);
    cudaGetSymbolAddress(&p_woh, g_wo_hi);

    // opt-in to >48KB dynamic smem (non-stream calls: capture-safe)
    cudaFuncSetAttribute(attn_tf32,
                         cudaFuncAttributeMaxDynamicSharedMemorySize,
                         ATTN_SMEM);
    cudaFuncSetAttribute(pgemm<2>,
                         cudaFuncAttributeMaxDynamicSharedMemorySize,
                         PGEMM_SMEM_2);
    cudaFuncSetAttribute(pgemm<1>,
                         cudaFuncAttributeMaxDynamicSharedMemorySize,
                         PGEMM_SMEM_1);

    const int MR = BB * NN;   // 8192 rows

    // 0) pack x (tf32 hi) and W_qkv (exact hi+lo split)
    pack_a<<<(MR / 16) * (DIM / 8) / 8, 256>>>(x, (unsigned*)p_xp, DIM);
    pack_b<<<(THC / 8) * (DIM / 16) / 8, 256>>>(
        wqkv, (unsigned*)p_wqh, (unsigned*)p_wql, DIM, THC);

    // 1) qkv = x_hi @ (W_hi + W_lo)  (wide 256x64 tile)
    pgemm<2><<<dim3(THC / 64, MR / 256), 256, PGEMM_SMEM_2>>>(
        (const unsigned*)p_xp, (const unsigned*)p_wqh, (const unsigned*)p_wql,
        (float*)p_qkv, MR, THC, DIM);

    // 2) split + rotary + scale; K/V written fragment-major packed
    qkv_transform<<<(BB * HEADS * NN * 32) / 256, 256>>>();

    // 3) fused flash attention (pre-packed K/V); writes packed mid
    attn_tf32<<<dim3(NN / 128, HEADS, BB), 256, ATTN_SMEM>>>(bias);

    // 4) out = mid_hi @ Wout_hi (1x tf32, wide tile)
    pack_b<<<(DIM / 8) * (HIDDEN / 16) / 8, 256>>>(
        wout, (unsigned*)p_woh, (unsigned*)0, HIDDEN, DIM);
    pgemm<1><<<dim3(DIM / 64, MR / 256), 256, PGEMM_SMEM_1>>>(
        (const unsigned*)p_mp, (const unsigned*)p_woh, (const unsigned*)0,
        (float*)d_out, MR, DIM, HIDDEN);
}

// round 15
// speedup vs baseline: 1.4061x; 1.4061x over previous
#include <cuda_runtime.h>
#include <math.h>

// Problem constants
#define BB 4
#define NN 2048
#define DIM 512
#define HEADS 8
#define DH 64
#define HIDDEN 512          // HEADS*DH
#define THC 1536            // 3*HIDDEN

// ---------------- scratch (device globals: allocation-free rule) ----------
__device__ float    g_qkv[(size_t)BB * NN * THC];          // 48 MB
__device__ float    g_q  [(size_t)BB * HEADS * NN * DH];   // 16 MB
// fragment-major packed operands (tf32 bit patterns)
__device__ unsigned g_kp  [(size_t)BB * HEADS * NN * DH];  // 16 MB  K packed
__device__ unsigned g_vp  [(size_t)BB * HEADS * NN * DH];  // 16 MB  V packed
__device__ unsigned g_xp  [(size_t)BB * NN * DIM];         // 16 MB  x packed
__device__ unsigned g_wq_hi[(size_t)DIM * THC];            // 3 MB
__device__ unsigned g_mp  [(size_t)BB * NN * HIDDEN];      // 16 MB  mid packed
__device__ unsigned g_wo_hi[(size_t)HIDDEN * DIM];         // 1 MB

// inv_freq[i] = 10000^(-2i/64) = 10^(-i/8), correctly-rounded fp32
__constant__ float c_invfreq[32] = {
    1.0f,
    0.74989420933245582f, 0.56234132519034907f, 0.42169650342858220f,
    0.31622776601683794f, 0.23713737056616552f, 0.17782794100389228f,
    0.13335214321633240f, 0.1f,
    0.074989420933245582f, 0.056234132519034907f, 0.042169650342858220f,
    0.031622776601683794f, 0.023713737056616552f, 0.017782794100389228f,
    0.013335214321633240f, 0.01f,
    0.0074989420933245582f, 0.0056234132519034907f, 0.0042169650342858220f,
    0.0031622776601683794f, 0.0023713737056616552f, 0.0017782794100389228f,
    0.0013335214321633240f, 0.001f,
    0.00074989420933245582f, 0.00056234132519034907f, 0.00042169650342858220f,
    0.00031622776601683794f, 0.00023713737056616552f, 0.00017782794100389228f,
    0.00013335214321633240f
};

// ---------------- tf32 helpers ----------------
__device__ __forceinline__ unsigned cvt_tf32(float f) {
    unsigned r;
    asm("cvt.rna.tf32.f32 %0, %1;" : "=r"(r) : "f"(f));
    return r;
}

__device__ __forceinline__ void mma_tf32(float c[4],
                                         unsigned a0, unsigned a1,
                                         unsigned a2, unsigned a3,
                                         unsigned b0, unsigned b1) {
    asm volatile(
        "mma.sync.aligned.m16n8k8.row.col.f32.tf32.tf32.f32 "
        "{%0,%1,%2,%3}, {%4,%5,%6,%7}, {%8,%9}, {%0,%1,%2,%3};\n"
        : "+f"(c[0]), "+f"(c[1]), "+f"(c[2]), "+f"(c[3])
        : "r"(a0), "r"(a1), "r"(a2), "r"(a3), "r"(b0), "r"(b1));
}

__device__ __forceinline__ void cp16(void* dst_smem, const void* src_gmem) {
    unsigned s = (unsigned)__cvta_generic_to_shared(dst_smem);
    asm volatile("cp.async.cg.shared.global [%0], [%1], 16;"
                 :: "r"(s), "l"(src_gmem));
}
__device__ __forceinline__ void cp_commit() {
    asm volatile("cp.async.commit_group;");
}
__device__ __forceinline__ void cp_wait1() {
    asm volatile("cp.async.wait_group 1;");
}

// =====================================================================
// Pack kernels (proven): m16n8k8 fragment-major tf32 layout.
// A layout [M/16][K/8][128]; B layout [N/8][K/16][128].
// =====================================================================
__global__ __launch_bounds__(256)
void pack_a(const float* __restrict__ src, unsigned* __restrict__ dst, int K)
{
    const int gw   = (blockIdx.x * 256 + threadIdx.x) >> 5;
    const int lane = threadIdx.x & 31;
    const int KB   = K >> 3;
    const int mb   = gw / KB;
    const int kb   = gw - mb * KB;
    const int qg   = lane >> 2, q = lane & 3;
    const float* s = src + (size_t)(mb * 16 + qg) * K + kb * 8 + q;
    uint4 o;
    o.x = cvt_tf32(s[0]);
    o.y = cvt_tf32(s[(size_t)8 * K]);
    o.z = cvt_tf32(s[4]);
    o.w = cvt_tf32(s[(size_t)8 * K + 4]);
    *(uint4*)&dst[(size_t)gw * 128 + lane * 4] = o;
}

__global__ __launch_bounds__(256)
void pack_b(const float* __restrict__ src, unsigned* __restrict__ hi,
            int K, int N)
{
    const int gw   = (blockIdx.x * 256 + threadIdx.x) >> 5;
    const int lane = threadIdx.x & 31;
    const int KB2  = K >> 4;
    const int nb   = gw / KB2;
    const int kb2  = gw - nb * KB2;
    const int qg   = lane >> 2, q = lane & 3;
    const float* s = src + (size_t)(kb2 * 16 + q) * N + nb * 8 + qg;
    uint4 h;
    h.x = cvt_tf32(s[0]);
    h.y = cvt_tf32(s[(size_t)4 * N]);
    h.z = cvt_tf32(s[(size_t)8 * N]);
    h.w = cvt_tf32(s[(size_t)12 * N]);
    *(uint4*)&hi[(size_t)gw * 128 + lane * 4] = h;
}

// =====================================================================
// Packed tensor-core GEMM (proven R13 config): block 128m x 64n,
// 256 threads, K-step 32, 3-stage cp.async pipeline, ONE barrier/iter.
// 98KB smem -> 2 blocks/SM (PB=1 path only; hi plane).
// =====================================================================
#define ABUF 4096
#define BBUF 2048

__global__ __launch_bounds__(256)
void pgemm(const unsigned* __restrict__ Ap, const unsigned* __restrict__ Bh,
           float* __restrict__ C, int M, int Nc, int K)
{
    extern __shared__ unsigned sm[];
    unsigned* As  = sm;                // [3][ABUF]
    unsigned* Bhs = sm + 3 * ABUF;     // [3][BBUF]

    const int tid  = threadIdx.x;
    const int lane = tid & 31;
    const int w    = tid >> 5;
    const int qg   = lane >> 2;
    const int q    = lane & 3;
    const int m0   = blockIdx.y * 128;
    const int n0   = blockIdx.x * 64;
    const int KB   = K >> 3;
    const int KB2  = K >> 4;
    const int NK   = K >> 5;

    const unsigned* Ag  = Ap + (size_t)(m0 >> 4) * KB * 128;
    const unsigned* Bhg = Bh + (size_t)(n0 >> 3) * KB2 * 128;

    const int cw  = tid >> 5;
    const int lw4 = (tid & 31) * 4;

    auto issue_tile = [&](int it, int p) {
        const unsigned* ga = Ag + ((size_t)cw * KB + it * 4) * 128;
        unsigned* da = As + p * ABUF + cw * 512;
#pragma unroll
        for (int s = 0; s < 4; ++s)
            cp16(da + s * 128 + lw4, ga + s * 128 + lw4);
        const unsigned* gb = Bhg + ((size_t)cw * KB2 + it * 2) * 128;
        unsigned* db = Bhs + p * BBUF + cw * 256;
#pragma unroll
        for (int s = 0; s < 2; ++s)
            cp16(db + s * 128 + lw4, gb + s * 128 + lw4);
        cp_commit();
    };

    float C_[8][4];
#pragma unroll
    for (int nt = 0; nt < 8; ++nt)
#pragma unroll
        for (int j = 0; j < 4; ++j) C_[nt][j] = 0.f;

    issue_tile(0, 0);
    issue_tile(1, 1);
    cp_wait1();
    __syncthreads();

    for (int it = 0; it < NK; ++it) {
        const int p = it % 3;
        const int itn = (it + 2 < NK) ? it + 2 : NK - 1;
        issue_tile(itn, (it + 2) % 3);

        uint4 af[4];
#pragma unroll
        for (int kk = 0; kk < 4; ++kk)
            af[kk] = *(const uint4*)&As[p * ABUF + w * 512 + kk * 128 + lane * 4];
#pragma unroll
        for (int nt = 0; nt < 8; ++nt) {
            const unsigned* bb = &Bhs[p * BBUF + nt * 256 + lane * 4];
            uint4 b0 = *(const uint4*)bb;
            uint4 b1 = *(const uint4*)(bb + 128);
            mma_tf32(C_[nt], af[0].x, af[0].y, af[0].z, af[0].w, b0.x, b0.y);
            mma_tf32(C_[nt], af[1].x, af[1].y, af[1].z, af[1].w, b0.z, b0.w);
            mma_tf32(C_[nt], af[2].x, af[2].y, af[2].z, af[2].w, b1.x, b1.y);
            mma_tf32(C_[nt], af[3].x, af[3].y, af[3].z, af[3].w, b1.z, b1.w);
        }

        cp_wait1();
        __syncthreads();
    }

#pragma unroll
    for (int nt = 0; nt < 8; ++nt) {
        int col = n0 + nt * 8 + 2 * q;
        size_t row = (size_t)(m0 + w * 16 + qg);
        *(float2*)&C[row * Nc + col]       = make_float2(C_[nt][0], C_[nt][1]);
        *(float2*)&C[(row + 8) * Nc + col] = make_float2(C_[nt][2], C_[nt][3]);
    }
}

#define PGEMM_SMEM (4 * (3 * ABUF + 3 * BBUF))       // 73728 B

// =====================================================================
// QKV split + rotary (+ q scale). Q row-major; K/V fragment-packed.
// (unchanged from R13 — proven)
// =====================================================================
__global__ __launch_bounds__(256)
void qkv_transform()
{
    const int idx  = blockIdx.x * 256 + threadIdx.x;
    const int pair = idx & 31;
    const int n    = (idx >> 5) & (NN - 1);
    const int bh   = idx >> 16;
    const int b    = bh >> 3;
    const int h    = bh & 7;

    const float* src = g_qkv + (size_t)(b * NN + n) * THC;
    const int col = h * DH + pair * 2;

    float2 qv = *(const float2*)&src[col];
    float2 kv = *(const float2*)&src[HIDDEN + col];
    float2 vv = *(const float2*)&src[2 * HIDDEN + col];

    float fr = (float)n * c_invfreq[pair];
    float sn, cs;
    sincosf(fr, &sn, &cs);

    const float scale = 0.125f;
    float oq0 = (qv.x * cs - qv.y * sn) * scale;
    float oq1 = (qv.y * cs + qv.x * sn) * scale;
    float ok0 = kv.x * cs - kv.y * sn;
    float ok1 = kv.y * cs + kv.x * sn;

    const int d0 = pair * 2;
    const size_t bhbase = (size_t)bh * (NN * DH);

    size_t o = bhbase + (size_t)n * DH + d0;
    g_q[o] = oq0; g_q[o + 1] = oq1;

    {
        const int qgk = n & 7, nbk = n >> 3;
        const int kb2 = d0 >> 4;
        size_t kbase = bhbase + ((size_t)nbk * 4 + kb2) * 128;
        int w0 = ((qgk << 2) | (d0 & 3)) * 4 + ((d0 & 15) >> 2);
        int w1 = ((qgk << 2) | ((d0 + 1) & 3)) * 4 + (((d0 + 1) & 15) >> 2);
        g_kp[kbase + w0] = cvt_tf32(ok0);
        g_kp[kbase + w1] = cvt_tf32(ok1);
    }

    {
        const int qv_ = n & 3, rv = (n & 15) >> 2, kb2v = n >> 4;
        const int nb0 = d0 >> 3, qg0 = d0 & 7;
        size_t vbase = bhbase + ((size_t)nb0 * 128 + kb2v) * 128;
        g_vp[vbase + ((qg0 << 2) | qv_) * 4 + rv]       = cvt_tf32(vv.x);
        g_vp[vbase + (((qg0 + 1) << 2) | qv_) * 4 + rv] = cvt_tf32(vv.y);
    }
}

// =====================================================================
// Fused flash attention, tf32 tensor cores, pre-packed K/V.
// (unchanged from R13 — proven)
// =====================================================================
#define CHUNK_WORDS 4096
#define ATTN_SMEM (3 * CHUNK_WORDS * 4)   // 49152 B

__global__ __launch_bounds__(256, 2)
void attn_tf32(const float* __restrict__ bias)
{
    extern __shared__ unsigned sm[];

    const int tid  = threadIdx.x;
    const int lane = tid & 31;
    const int w    = tid >> 5;
    const int qg   = lane >> 2;
    const int q    = lane & 3;
    const int qblk = blockIdx.x * 128;
    const int h    = blockIdx.y;
    const int b    = blockIdx.z;
    const int bh   = b * HEADS + h;
    const unsigned* Kbh = g_kp + (size_t)bh * (NN * DH);
    const unsigned* Vbh = g_vp + (size_t)bh * (NN * DH);
    const float* biasw = bias + (size_t)h * NN * NN
                              + (size_t)(qblk + w * 16) * NN;

    const int koff = tid * 8;
    const int vreg = tid >> 5;
    const int voff = (tid & 31) * 8;

    auto issue_chunk = [&](int j, int p) {
        unsigned* dst = sm + p * CHUNK_WORDS;
        const unsigned* sk = Kbh + (size_t)j * 2048 + koff;
        cp16(dst + koff,     sk);
        cp16(dst + koff + 4, sk + 4);
        unsigned* dv = dst + 2048 + vreg * 256 + voff;
        const unsigned* sv = Vbh + ((size_t)vreg * 128 + j * 2) * 128 + voff;
        cp16(dv,     sv);
        cp16(dv + 4, sv + 4);
        cp_commit();
    };

    unsigned qa[8][4];
    {
        const float* Qp = g_q + (size_t)bh * (NN * DH)
                        + (size_t)(qblk + w * 16) * DH;
#pragma unroll
        for (int kc = 0; kc < 8; ++kc) {
            qa[kc][0] = cvt_tf32(Qp[(size_t)qg       * DH + kc * 8 + q]);
            qa[kc][1] = cvt_tf32(Qp[(size_t)(qg + 8) * DH + kc * 8 + q]);
            qa[kc][2] = cvt_tf32(Qp[(size_t)qg       * DH + kc * 8 + q + 4]);
            qa[kc][3] = cvt_tf32(Qp[(size_t)(qg + 8) * DH + kc * 8 + q + 4]);
        }
    }

    issue_chunk(0, 0);
    issue_chunk(1, 1);

    float S[4][4];
#pragma unroll
    for (int t = 0; t < 4; ++t) {
        float2 blo = *(const float2*)&biasw[(size_t)qg       * NN + t * 8 + 2 * q];
        float2 bhi = *(const float2*)&biasw[(size_t)(qg + 8) * NN + t * 8 + 2 * q];
        S[t][0] = blo.x; S[t][1] = blo.y;
        S[t][2] = bhi.x; S[t][3] = bhi.y;
    }

    cp_wait1();
    __syncthreads();

    float O[8][4];
#pragma unroll
    for (int n = 0; n < 8; ++n)
#pragma unroll
        for (int j = 0; j < 4; ++j) O[n][j] = 0.f;
    float m0 = -INFINITY, m1 = -INFINITY, l0 = 0.f, l1 = 0.f;

    const int srcA = (lane & ~3) | (q >> 1);
    const int srcB = srcA | 2;

    for (int j = 0; j < 64; ++j) {
        const int p = j % 3;
        issue_chunk((j + 2 < 64) ? j + 2 : 63, (j + 2) % 3);

        const unsigned* KF = sm + p * CHUNK_WORDS;
#pragma unroll
        for (int t = 0; t < 4; ++t) {
            uint4 k0 = *(const uint4*)&KF[t * 512 +   0 + lane * 4];
            uint4 k1 = *(const uint4*)&KF[t * 512 + 128 + lane * 4];
            uint4 k2 = *(const uint4*)&KF[t * 512 + 256 + lane * 4];
            uint4 k3 = *(const uint4*)&KF[t * 512 + 384 + lane * 4];
            mma_tf32(S[t], qa[0][0], qa[0][1], qa[0][2], qa[0][3], k0.x, k0.y);
            mma_tf32(S[t], qa[1][0], qa[1][1], qa[1][2], qa[1][3], k0.z, k0.w);
            mma_tf32(S[t], qa[2][0], qa[2][1], qa[2][2], qa[2][3], k1.x, k1.y);
            mma_tf32(S[t], qa[3][0], qa[3][1], qa[3][2], qa[3][3], k1.z, k1.w);
            mma_tf32(S[t], qa[4][0], qa[4][1], qa[4][2], qa[4][3], k2.x, k2.y);
            mma_tf32(S[t], qa[5][0], qa[5][1], qa[5][2], qa[5][3], k2.z, k2.w);
            mma_tf32(S[t], qa[6][0], qa[6][1], qa[6][2], qa[6][3], k3.x, k3.y);
            mma_tf32(S[t], qa[7][0], qa[7][1], qa[7][2], qa[7][3], k3.z, k3.w);
        }

        float cm0 = -INFINITY, cm1 = -INFINITY;
#pragma unroll
        for (int t = 0; t < 4; ++t) {
            cm0 = fmaxf(cm0, fmaxf(S[t][0], S[t][1]));
            cm1 = fmaxf(cm1, fmaxf(S[t][2], S[t][3]));
        }
        cm0 = fmaxf(cm0, __shfl_xor_sync(0xffffffffu, cm0, 1));
        cm0 = fmaxf(cm0, __shfl_xor_sync(0xffffffffu, cm0, 2));
        cm1 = fmaxf(cm1, __shfl_xor_sync(0xffffffffu, cm1, 1));
        cm1 = fmaxf(cm1, __shfl_xor_sync(0xffffffffu, cm1, 2));

        float mn0 = fmaxf(m0, cm0), mn1 = fmaxf(m1, cm1);
        float al0 = __expf(m0 - mn0), al1 = __expf(m1 - mn1);
        m0 = mn0; m1 = mn1;

        float s0 = 0.f, s1 = 0.f;
#pragma unroll
        for (int t = 0; t < 4; ++t) {
            S[t][0] = __expf(S[t][0] - mn0);
            S[t][1] = __expf(S[t][1] - mn0);
            S[t][2] = __expf(S[t][2] - mn1);
            S[t][3] = __expf(S[t][3] - mn1);
            s0 += S[t][0] + S[t][1];
            s1 += S[t][2] + S[t][3];
        }
        s0 += __shfl_xor_sync(0xffffffffu, s0, 1);
        s0 += __shfl_xor_sync(0xffffffffu, s0, 2);
        s1 += __shfl_xor_sync(0xffffffffu, s1, 1);
        s1 += __shfl_xor_sync(0xffffffffu, s1, 2);
        l0 = l0 * al0 + s0;
        l1 = l1 * al1 + s1;
#pragma unroll
        for (int n = 0; n < 8; ++n) {
            O[n][0] *= al0; O[n][1] *= al0;
            O[n][2] *= al1; O[n][3] *= al1;
        }

        unsigned pf[4][4];
#pragma unroll
        for (int t = 0; t < 4; ++t) {
            unsigned p0 = cvt_tf32(S[t][0]);
            unsigned p1 = cvt_tf32(S[t][1]);
            unsigned p2 = cvt_tf32(S[t][2]);
            unsigned p3 = cvt_tf32(S[t][3]);
            unsigned u0 = __shfl_sync(0xffffffffu, p0, srcA);
            unsigned u1 = __shfl_sync(0xffffffffu, p1, srcA);
            unsigned v0 = __shfl_sync(0xffffffffu, p0, srcB);
            unsigned v1 = __shfl_sync(0xffffffffu, p1, srcB);
            unsigned w0 = __shfl_sync(0xffffffffu, p2, srcA);
            unsigned w1 = __shfl_sync(0xffffffffu, p3, srcA);
            unsigned x0 = __shfl_sync(0xffffffffu, p2, srcB);
            unsigned x1 = __shfl_sync(0xffffffffu, p3, srcB);
            pf[t][0] = (q & 1) ? u1 : u0;
            pf[t][1] = (q & 1) ? w1 : w0;
            pf[t][2] = (q & 1) ? v1 : v0;
            pf[t][3] = (q & 1) ? x1 : x0;
        }

        const unsigned* VF = sm + p * CHUNK_WORDS + 2048;
#pragma unroll
        for (int nt = 0; nt < 8; ++nt) {
            uint4 v0 = *(const uint4*)&VF[nt * 256 +   0 + lane * 4];
            uint4 v1 = *(const uint4*)&VF[nt * 256 + 128 + lane * 4];
            mma_tf32(O[nt], pf[0][0], pf[0][1], pf[0][2], pf[0][3], v0.x, v0.y);
            mma_tf32(O[nt], pf[1][0], pf[1][1], pf[1][2], pf[1][3], v0.z, v0.w);
            mma_tf32(O[nt], pf[2][0], pf[2][1], pf[2][2], pf[2][3], v1.x, v1.y);
            mma_tf32(O[nt], pf[3][0], pf[3][1], pf[3][2], pf[3][3], v1.z, v1.w);
        }

        {
            const int j0n = ((j + 1 < 64) ? j + 1 : 63) * 32;
#pragma unroll
            for (int t = 0; t < 4; ++t) {
                float2 blo = *(const float2*)
                    &biasw[(size_t)qg       * NN + j0n + t * 8 + 2 * q];
                float2 bhi = *(const float2*)
                    &biasw[(size_t)(qg + 8) * NN + j0n + t * 8 + 2 * q];
                S[t][0] = blo.x; S[t][1] = blo.y;
                S[t][2] = bhi.x; S[t][3] = bhi.y;
            }
        }

        cp_wait1();
        __syncthreads();
    }

    const float il0 = 1.f / l0, il1 = 1.f / l1;
    const int mb = (b * NN + qblk + w * 16) >> 4;
#pragma unroll
    for (int nt = 0; nt < 8; ++nt) {
        unsigned f0 = __float_as_uint(O[nt][0] * il0);
        unsigned f1 = __float_as_uint(O[nt][1] * il0);
        unsigned f2 = __float_as_uint(O[nt][2] * il1);
        unsigned f3 = __float_as_uint(O[nt][3] * il1);
        unsigned u0 = __shfl_sync(0xffffffffu, f0, srcA);
        unsigned u1 = __shfl_sync(0xffffffffu, f1, srcA);
        unsigned w0 = __shfl_sync(0xffffffffu, f2, srcA);
        unsigned w1 = __shfl_sync(0xffffffffu, f3, srcA);
        unsigned x0 = __shfl_sync(0xffffffffu, f0, srcB);
        unsigned x1 = __shfl_sync(0xffffffffu, f1, srcB);
        unsigned y0 = __shfl_sync(0xffffffffu, f2, srcB);
        unsigned y1 = __shfl_sync(0xffffffffu, f3, srcB);
        uint4 o;
        o.x = cvt_tf32(__uint_as_float((q & 1) ? u1 : u0));
        o.y = cvt_tf32(__uint_as_float((q & 1) ? w1 : w0));
        o.z = cvt_tf32(__uint_as_float((q & 1) ? x1 : x0));
        o.w = cvt_tf32(__uint_as_float((q & 1) ? y1 : y0));
        const int kb = h * 8 + nt;
        *(uint4*)&g_mp[((size_t)mb * (HIDDEN / 8) + kb) * 128 + lane * 4] = o;
    }
}

// =====================================================================
extern "C" void kernel_launch(void* const* d_in, const int* in_sizes, int n_in,
                              void* d_out, int out_size)
{
    const float *x = nullptr, *bias = nullptr, *wqkv = nullptr, *wout = nullptr;
    for (int i = 0; i < n_in; ++i) {
        switch (in_sizes[i]) {
            case 4194304:  x    = (const float*)d_in[i]; break;  // x [4,2048,512]
            case 33554432: bias = (const float*)d_in[i]; break;  // pos_bias [8,2048,2048]
            case 786432:   wqkv = (const float*)d_in[i]; break;  // W_qkv [512,1536]
            case 262144:   wout = (const float*)d_in[i]; break;  // W_out [512,512]
        }
    }

    void *p_qkv = nullptr;
    void *p_xp = nullptr, *p_wqh = nullptr;
    void *p_mp = nullptr, *p_woh = nullptr;
    cudaGetSymbolAddress(&p_qkv, g_qkv);
    cudaGetSymbolAddress(&p_xp,  g_xp);
    cudaGetSymbolAddress(&p_wqh, g_wq_hi);
    cudaGetSymbolAddress(&p_mp,  g_mp);
    cudaGetSymbolAddress(&p_woh, g_wo_hi);

    // opt-in to >48KB dynamic smem (non-stream calls: capture-safe)
    cudaFuncSetAttribute(attn_tf32,
                         cudaFuncAttributeMaxDynamicSharedMemorySize,
                         ATTN_SMEM);
    cudaFuncSetAttribute(pgemm,
                         cudaFuncAttributeMaxDynamicSharedMemorySize,
                         PGEMM_SMEM);

    const int MR = BB * NN;   // 8192 rows

    // 0) pack x and W_qkv (both tf32 hi)
    pack_a<<<(MR / 16) * (DIM / 8) / 8, 256>>>(x, (unsigned*)p_xp, DIM);
    pack_b<<<(THC / 8) * (DIM / 16) / 8, 256>>>(
        wqkv, (unsigned*)p_wqh, DIM, THC);

    // 1) qkv = x_hi @ W_hi (1x tf32)
    pgemm<<<dim3(THC / 64, MR / 128), 256, PGEMM_SMEM>>>(
        (const unsigned*)p_xp, (const unsigned*)p_wqh,
        (float*)p_qkv, MR, THC, DIM);

    // 2) split + rotary + scale; K/V written fragment-major packed
    qkv_transform<<<(BB * HEADS * NN * 32) / 256, 256>>>();

    // 3) fused flash attention (pre-packed K/V); writes packed mid
    attn_tf32<<<dim3(NN / 128, HEADS, BB), 256, ATTN_SMEM>>>(bias);

    // 4) out = mid_hi @ Wout_hi (1x tf32)
    pack_b<<<(DIM / 8) * (HIDDEN / 16) / 8, 256>>>(
        wout, (unsigned*)p_woh, HIDDEN, DIM);
    pgemm<<<dim3(DIM / 64, MR / 128), 256, PGEMM_SMEM>>>(
        (const unsigned*)p_mp, (const unsigned*)p_woh,
        (float*)d_out, MR, DIM, HIDDEN);
}